// round 1
// baseline (speedup 1.0000x reference)
#include <cuda_runtime.h>
#include <cuda_fp16.h>
#include <cstdint>

#define MROWS 8192   // B*N tokens
#define KPROT 8192   // prototypes
#define DDIM  768
#define INV_TT (1.0f/0.07f)
#define INV_ST 10.0f
#define SK_EPS 1e-8f
#define SHIFT  9.0f   // fixed stabilization shift (>= max |L|/temp by Cauchy-Schwarz)

// ---------------- scratch (static device globals; no allocation) -------------
static __device__ __half g_Lt[(size_t)MROWS * KPROT];   // teacher logits fp16 (128MB)
static __device__ __half g_Ls[(size_t)MROWS * KPROT];   // student logits fp16 (128MB)
static __device__ float  g_tn[MROWS * DDIM];
static __device__ float  g_sn[MROWS * DDIM];
static __device__ float  g_wn[KPROT * DDIM];
static __device__ float  g_S[KPROT];
static __device__ float  g_r[KPROT];
static __device__ float  g_c[MROWS];
static __device__ float  g_msk[MROWS];
static __device__ int    g_maxd[KPROT];
static __device__ float  g_acc[4];   // 0:teacher 1:clust_num 2:mask_sum 3:koleo_logsum
static __device__ int    g_maskmode; // 0:u8 1:i32 2:f32

// ---------------- reductions -------------------------------------------------
__device__ __forceinline__ float warpSum(float v) {
#pragma unroll
    for (int o = 16; o > 0; o >>= 1) v += __shfl_down_sync(0xffffffffu, v, o);
    return v;
}
// valid in thread 0; safe to call repeatedly
__device__ float blockSum(float v) {
    __shared__ float sb[32];
    int lane = threadIdx.x & 31, w = threadIdx.x >> 5;
    v = warpSum(v);
    __syncthreads();
    if (lane == 0) sb[w] = v;
    __syncthreads();
    int nw = (blockDim.x + 31) >> 5;
    v = (threadIdx.x < nw) ? sb[threadIdx.x] : 0.f;
    if (w == 0) v = warpSum(v);
    return v;
}

// ---------------- mask handling ----------------------------------------------
__global__ void detect_mask_kernel(const unsigned char* __restrict__ p) {
    __shared__ int c0, c1, c23;
    if (threadIdx.x == 0) { c0 = 0; c1 = 0; c23 = 0; }
    __syncthreads();
    int l0 = 0, l1 = 0, l23 = 0;
    for (int i = threadIdx.x; i < MROWS; i += blockDim.x) {  // first 8192 bytes: in-bounds
        unsigned char b = p[i];                              // under every interpretation
        if (b) { int r = i & 3; if (r == 0) l0++; else if (r == 1) l1++; else l23++; }
    }
    atomicAdd(&c0, l0); atomicAdd(&c1, l1); atomicAdd(&c23, l23);
    __syncthreads();
    if (threadIdx.x == 0) {
        int mode;
        if (c1 == 0 && c23 == 0) mode = (c0 > 0) ? 1 : 0;  // pure word pattern -> i32 (or all-zero -> u8 safe)
        else if (c1 == 0)        mode = 2;                 // f32 1.0 pattern (0x3F80 high bytes)
        else                     mode = 0;                 // bytes random 0/1 -> u8/bool
        g_maskmode = mode;
    }
}
__global__ void build_mask_kernel(const void* __restrict__ p) {
    int m = blockIdx.x * blockDim.x + threadIdx.x;
    if (m >= MROWS) return;
    int mode = g_maskmode;
    float v;
    if (mode == 1)      v = (((const int*)p)[m] != 0) ? 1.f : 0.f;
    else if (mode == 2) v = (((const float*)p)[m] != 0.f) ? 1.f : 0.f;
    else                v = (((const unsigned char*)p)[m] != 0) ? 1.f : 0.f;
    g_msk[m] = v;
}

// ---------------- init --------------------------------------------------------
__global__ void init_kernel() {
    int i = blockIdx.x * blockDim.x + threadIdx.x;
    if (i < KPROT) { g_S[i] = 0.f; g_r[i] = 1.f; g_maxd[i] = 0; }
    if (i < MROWS) { g_c[i] = 1.f; }
    if (i < 4)     { g_acc[i] = 0.f; }
}

// ---------------- row L2-normalize --------------------------------------------
__global__ void normalize_rows_kernel(const float* __restrict__ in, int which) {
    float* out = (which == 0) ? g_tn : (which == 1) ? g_sn : g_wn;
    int row = blockIdx.x;
    const float* x = in + (size_t)row * DDIM;
    float ss = 0.f;
    for (int d = threadIdx.x; d < DDIM; d += blockDim.x) { float v = x[d]; ss += v * v; }
    ss = blockSum(ss);
    __shared__ float sinv;
    if (threadIdx.x == 0) sinv = 1.f / fmaxf(sqrtf(ss), 1e-12f);
    __syncthreads();
    float inv = sinv;
    float* o = out + (size_t)row * DDIM;
    for (int d = threadIdx.x; d < DDIM; d += blockDim.x) o[d] = x[d] * inv;
}

// ---------------- GEMM (NT, A[M,D] x B[K,D]^T), fp32 SIMT ---------------------
// MODE 0: A=g_tn, B=W   -> store g_Lt fp16, fuse S1_k = sum_m exp(L/tt - shift)
// MODE 1: A=g_sn, B=W   -> store g_Ls fp16
// MODE 2: A=B=g_wn      -> no store; per-row off-diagonal max -> g_maxd (atomicMax)
template <int MODE>
__global__ void __launch_bounds__(256)
gemm_nt_kernel(const float* __restrict__ Bext) {
    const float* A = (MODE == 0) ? g_tn : (MODE == 1) ? g_sn : g_wn;
    const float* B = (MODE == 2) ? g_wn : Bext;
    __half* C = (MODE == 0) ? g_Lt : g_Ls;

    __shared__ float As[16][132];
    __shared__ float Bs[16][132];
    int tid = threadIdx.x;
    int tx = tid & 15, ty = tid >> 4;
    int m0 = blockIdx.y * 128, n0 = blockIdx.x * 128;
    int ldr = tid >> 2;             // 0..63
    int ldc = (tid & 3) << 2;       // 0,4,8,12

    const float* Ap = A + (size_t)(m0 + ldr) * DDIM + ldc;
    const float* Bp = B + (size_t)(n0 + ldr) * DDIM + ldc;

    float acc[8][8];
#pragma unroll
    for (int i = 0; i < 8; i++)
#pragma unroll
        for (int j = 0; j < 8; j++) acc[i][j] = 0.f;

    for (int k0 = 0; k0 < DDIM; k0 += 16) {
        float4 a0 = *(const float4*)(Ap + k0);
        float4 a1 = *(const float4*)(Ap + k0 + (size_t)64 * DDIM);
        float4 b0 = *(const float4*)(Bp + k0);
        float4 b1 = *(const float4*)(Bp + k0 + (size_t)64 * DDIM);
        As[ldc + 0][ldr] = a0.x; As[ldc + 1][ldr] = a0.y; As[ldc + 2][ldr] = a0.z; As[ldc + 3][ldr] = a0.w;
        As[ldc + 0][ldr + 64] = a1.x; As[ldc + 1][ldr + 64] = a1.y; As[ldc + 2][ldr + 64] = a1.z; As[ldc + 3][ldr + 64] = a1.w;
        Bs[ldc + 0][ldr] = b0.x; Bs[ldc + 1][ldr] = b0.y; Bs[ldc + 2][ldr] = b0.z; Bs[ldc + 3][ldr] = b0.w;
        Bs[ldc + 0][ldr + 64] = b1.x; Bs[ldc + 1][ldr + 64] = b1.y; Bs[ldc + 2][ldr + 64] = b1.z; Bs[ldc + 3][ldr + 64] = b1.w;
        __syncthreads();
#pragma unroll
        for (int kk = 0; kk < 16; kk++) {
            float4 av0 = *(const float4*)&As[kk][ty * 8];
            float4 av1 = *(const float4*)&As[kk][ty * 8 + 4];
            float4 bv0 = *(const float4*)&Bs[kk][tx * 8];
            float4 bv1 = *(const float4*)&Bs[kk][tx * 8 + 4];
            float a[8] = {av0.x, av0.y, av0.z, av0.w, av1.x, av1.y, av1.z, av1.w};
            float b[8] = {bv0.x, bv0.y, bv0.z, bv0.w, bv1.x, bv1.y, bv1.z, bv1.w};
#pragma unroll
            for (int i = 0; i < 8; i++)
#pragma unroll
                for (int j = 0; j < 8; j++) acc[i][j] = fmaf(a[i], b[j], acc[i][j]);
        }
        __syncthreads();
    }

    if (MODE == 0 || MODE == 1) {
#pragma unroll
        for (int i = 0; i < 8; i++) {
            __align__(16) __half h[8];
#pragma unroll
            for (int j = 0; j < 8; j++) h[j] = __float2half(acc[i][j]);
            *(uint4*)&C[(size_t)(m0 + ty * 8 + i) * KPROT + n0 + tx * 8] = *(uint4*)h;
        }
    }
    if (MODE == 0) {
        // fused S1_k = sum over the 128 m-rows of exp(L/tt - shift)
        float cs[8];
#pragma unroll
        for (int j = 0; j < 8; j++) {
            float s = 0.f;
#pragma unroll
            for (int i = 0; i < 8; i++) s += __expf(acc[i][j] * INV_TT - SHIFT);
            cs[j] = s;
        }
#pragma unroll
        for (int j = 0; j < 8; j++) As[ty][tx * 8 + j] = cs[j];
        __syncthreads();
        if (tid < 128) {
            float s = 0.f;
#pragma unroll
            for (int t = 0; t < 16; t++) s += As[t][tid];
            atomicAdd(&g_S[n0 + tid], s);
        }
    }
    if (MODE == 2) {
        float* red = &Bs[0][0];  // 16*132 = 2112 floats >= 2048
        float rm[8];
#pragma unroll
        for (int i = 0; i < 8; i++) {
            int gm = m0 + ty * 8 + i;
            float mx = -2.f;
#pragma unroll
            for (int j = 0; j < 8; j++) {
                int gk = n0 + tx * 8 + j;
                float v = (gm == gk) ? -2.f : acc[i][j];
                mx = fmaxf(mx, v);
            }
            rm[i] = mx;
        }
#pragma unroll
        for (int i = 0; i < 8; i++) red[(ty * 8 + i) * 16 + tx] = rm[i];
        __syncthreads();
        if (tid < 128) {
            float mx = -2.f;
#pragma unroll
            for (int t = 0; t < 16; t++) mx = fmaxf(mx, red[tid * 16 + t]);
            // bias by +2 -> positive floats are order-preserving as ints
            atomicMax(&g_maxd[m0 + tid], __float_as_int(mx + 2.0f));
        }
    }
}

// ---------------- helpers ------------------------------------------------------
__device__ __forceinline__ void h8_to_f(const uint4& u, float f[8]) {
    __half2 a = *(const __half2*)&u.x, b = *(const __half2*)&u.y;
    __half2 c = *(const __half2*)&u.z, d = *(const __half2*)&u.w;
    float2 fa = __half22float2(a), fb = __half22float2(b);
    float2 fc = __half22float2(c), fd = __half22float2(d);
    f[0] = fa.x; f[1] = fa.y; f[2] = fb.x; f[3] = fb.y;
    f[4] = fc.x; f[5] = fc.y; f[6] = fd.x; f[7] = fd.y;
}

// ---------------- Sinkhorn passes -----------------------------------------------
// r <- r/(r*S + eps); also zero S for next accumulation
__global__ void r_update_kernel() {
    int k = blockIdx.x * blockDim.x + threadIdx.x;
    if (k < KPROT) {
        float r = g_r[k], s = g_S[k];
        g_r[k] = r / (r * s + SK_EPS);
        g_S[k] = 0.f;
    }
}

// T_m = sum_k E*r ; c <- c/(c*T + eps)
__global__ void pass_T_kernel() {
    int m = blockIdx.x;
    const uint4* row = (const uint4*)(g_Lt + (size_t)m * KPROT);
    float t = 0.f;
    for (int i = threadIdx.x; i < KPROT / 8; i += blockDim.x) {
        uint4 u = row[i];
        float lt[8];
        h8_to_f(u, lt);
        float4 r0 = *(const float4*)(g_r + i * 8);
        float4 r1 = *(const float4*)(g_r + i * 8 + 4);
        float rr[8] = {r0.x, r0.y, r0.z, r0.w, r1.x, r1.y, r1.z, r1.w};
#pragma unroll
        for (int j = 0; j < 8; j++) t += __expf(lt[j] * INV_TT - SHIFT) * rr[j];
    }
    t = blockSum(t);
    if (threadIdx.x == 0) {
        float co = g_c[m];
        g_c[m] = co / (co * t + SK_EPS);
    }
}

// S_k += sum over 64 rows of E*c
__global__ void pass_S_kernel() {
    int k = blockIdx.x * blockDim.x + threadIdx.x;
    int m0 = blockIdx.y * 64;
    __shared__ float cs[64];
    if (threadIdx.x < 64) cs[threadIdx.x] = g_c[m0 + threadIdx.x];
    __syncthreads();
    float s = 0.f;
#pragma unroll 4
    for (int r = 0; r < 64; r++) {
        float lt = __half2float(g_Lt[(size_t)(m0 + r) * KPROT + k]);
        s += __expf(lt * INV_TT - SHIFT) * cs[r];
    }
    atomicAdd(&g_S[k], s);
}

// ---------------- fused loss pass (one block per token row) ---------------------
__global__ void loss_kernel() {
    int m = blockIdx.x;
    const uint4* ltr = (const uint4*)(g_Lt + (size_t)m * KPROT);
    const uint4* lsr = (const uint4*)(g_Ls + (size_t)m * KPROT);
    float A = 0.f, Bv = 0.f, Dv = 0.f, Cv = 0.f, F = 0.f;
    for (int i = threadIdx.x; i < KPROT / 8; i += blockDim.x) {
        uint4 ut = ltr[i], us = lsr[i];
        float lt[8], ls[8];
        h8_to_f(ut, lt);
        h8_to_f(us, ls);
        float4 r0 = *(const float4*)(g_r + i * 8);
        float4 r1 = *(const float4*)(g_r + i * 8 + 4);
        float rr[8] = {r0.x, r0.y, r0.z, r0.w, r1.x, r1.y, r1.z, r1.w};
#pragma unroll
        for (int j = 0; j < 8; j++) {
            float e  = __expf(lt[j] * INV_TT - SHIFT);
            float er = e * rr[j];
            A  += er;
            Bv += er * lt[j];
            Dv += e;
            Cv += er * ls[j];
            F  += __expf(ls[j] * INV_ST);
        }
    }
    A  = blockSum(A);
    Bv = blockSum(Bv);
    Dv = blockSum(Dv);
    Cv = blockSum(Cv);
    F  = blockSum(F);
    if (threadIdx.x == 0) {
        float co = g_c[m];                       // c2
        float c3 = co / (co * A + SK_EPS);       // final Sinkhorn column scale (A == T3)
        float lse_t = logf(Dv) + SHIFT;          // logsumexp_k(L/tt)
        float lse_s = logf(F);                   // logsumexp_k(Ls/st)
        float tpt = c3 * (A * lse_t - Bv * INV_TT);  // -sum_k Q*logp_t
        float spt = c3 * (A * lse_s - Cv * INV_ST);  // -sum_k Q*logp_s
        atomicAdd(&g_acc[0], tpt);
        float mm = g_msk[m];
        atomicAdd(&g_acc[1], mm * spt);
        atomicAdd(&g_acc[2], mm);
    }
}

// ---------------- koleo finish ----------------------------------------------
__global__ void koleo_kernel() {
    int k = blockIdx.x * blockDim.x + threadIdx.x;
    float term = 0.f;
    if (k < KPROT) {
        float g = __int_as_float(g_maxd[k]) - 2.0f;       // max off-diag dot
        float d = sqrtf(fmaxf(2.f - 2.f * g, 0.f));       // ||x - x_nn|| for unit vecs
        term = logf(d + 1e-8f);
    }
    term = blockSum(term);
    if (threadIdx.x == 0) atomicAdd(&g_acc[3], term);
}

__global__ void finalize_kernel(float* __restrict__ out) {
    if (threadIdx.x == 0) {
        out[0] = g_acc[1] / fmaxf(g_acc[2], 1.f);    // clustering loss
        out[1] = g_acc[0] * (1.f / (float)MROWS);    // teacher proto loss
        out[2] = -g_acc[3] * (1.f / (float)KPROT);   // koleo
    }
}

// ---------------- launch --------------------------------------------------------
extern "C" void kernel_launch(void* const* d_in, const int* in_sizes, int n_in,
                              void* d_out, int out_size) {
    // identify the mask input by element count (8192); others keep dict order t, s, W
    int midx = -1;
    for (int i = 0; i < n_in; i++)
        if (in_sizes[i] == MROWS) { midx = i; break; }
    if (midx < 0) midx = 2;
    int others[3], no = 0;
    for (int i = 0; i < n_in && no < 3; i++)
        if (i != midx) others[no++] = i;

    const float* teacher = (const float*)d_in[others[0]];
    const float* student = (const float*)d_in[others[1]];
    const float* W       = (const float*)d_in[others[2]];
    const void*  mask    = d_in[midx];

    detect_mask_kernel<<<1, 256>>>((const unsigned char*)mask);
    build_mask_kernel<<<32, 256>>>(mask);
    init_kernel<<<32, 256>>>();

    normalize_rows_kernel<<<MROWS, 256>>>(teacher, 0);
    normalize_rows_kernel<<<MROWS, 256>>>(student, 1);
    normalize_rows_kernel<<<KPROT, 256>>>(W, 2);

    dim3 gg(KPROT / 128, MROWS / 128);
    gemm_nt_kernel<0><<<gg, 256>>>(W);        // teacher logits + fused S1
    gemm_nt_kernel<1><<<gg, 256>>>(W);        // student logits
    gemm_nt_kernel<2><<<gg, 256>>>(nullptr);  // koleo nn-max (fused)

    // Sinkhorn (factored scalings): r1 from S1; then T,S alternation; T3 fused in loss
    r_update_kernel<<<KPROT / 256, 256>>>();              // r1 (also zeros S)
    pass_T_kernel<<<MROWS, 256>>>();                      // c1
    pass_S_kernel<<<dim3(KPROT / 256, MROWS / 64), 256>>>();  // S2
    r_update_kernel<<<KPROT / 256, 256>>>();              // r2
    pass_T_kernel<<<MROWS, 256>>>();                      // c2
    pass_S_kernel<<<dim3(KPROT / 256, MROWS / 64), 256>>>();  // S3
    r_update_kernel<<<KPROT / 256, 256>>>();              // r3

    loss_kernel<<<MROWS, 256>>>();                        // T3 + c3 + both CE losses
    koleo_kernel<<<KPROT / 256, 256>>>();
    finalize_kernel<<<1, 32>>>((float*)d_out);
    (void)out_size;
}

// round 3
// speedup vs baseline: 4.8566x; 4.8566x over previous
#include <cuda_runtime.h>
#include <cuda_fp16.h>
#include <cstdint>

#define MROWS 8192   // B*N tokens
#define KPROT 8192   // prototypes
#define DDIM  768
#define INV_TT (1.0f/0.07f)
#define INV_ST 10.0f
#define SK_EPS 1e-8f
#define SHIFT  9.0f

// ---------------- scratch (static device globals; no allocation) -------------
static __device__ __align__(16) __half g_Lt[(size_t)MROWS * KPROT];
static __device__ __align__(16) __half g_Ls[(size_t)MROWS * KPROT];
static __device__ __align__(16) __half g_th[MROWS * DDIM];
static __device__ __align__(16) __half g_sh[MROWS * DDIM];
static __device__ __align__(16) __half g_whr[KPROT * DDIM];
static __device__ __align__(16) __half g_whn[KPROT * DDIM];
static __device__ float  g_S[KPROT];
static __device__ float  g_r[KPROT];
static __device__ float  g_c[MROWS];
static __device__ float  g_msk[MROWS];
static __device__ int    g_maxd[KPROT];
static __device__ float  g_acc[4];
static __device__ int    g_maskmode;

// ---------------- reductions ---------------------------------------------------
__device__ __forceinline__ float warpSum(float v) {
#pragma unroll
    for (int o = 16; o > 0; o >>= 1) v += __shfl_down_sync(0xffffffffu, v, o);
    return v;
}
__device__ float blockSum(float v) {
    __shared__ float sb[32];
    int lane = threadIdx.x & 31, w = threadIdx.x >> 5;
    v = warpSum(v);
    __syncthreads();
    if (lane == 0) sb[w] = v;
    __syncthreads();
    int nw = (blockDim.x + 31) >> 5;
    v = (threadIdx.x < nw) ? sb[threadIdx.x] : 0.f;
    if (w == 0) v = warpSum(v);
    return v;
}

// ---------------- mask handling -------------------------------------------------
__global__ void detect_mask_kernel(const unsigned char* __restrict__ p) {
    __shared__ int c0, c1, c23;
    if (threadIdx.x == 0) { c0 = 0; c1 = 0; c23 = 0; }
    __syncthreads();
    int l0 = 0, l1 = 0, l23 = 0;
    for (int i = threadIdx.x; i < MROWS; i += blockDim.x) {
        unsigned char b = p[i];
        if (b) { int r = i & 3; if (r == 0) l0++; else if (r == 1) l1++; else l23++; }
    }
    atomicAdd(&c0, l0); atomicAdd(&c1, l1); atomicAdd(&c23, l23);
    __syncthreads();
    if (threadIdx.x == 0) {
        int mode;
        if (c1 == 0 && c23 == 0) mode = (c0 > 0) ? 1 : 0;
        else if (c1 == 0)        mode = 2;
        else                     mode = 0;
        g_maskmode = mode;
    }
}
__global__ void build_mask_kernel(const void* __restrict__ p) {
    int m = blockIdx.x * blockDim.x + threadIdx.x;
    if (m >= MROWS) return;
    int mode = g_maskmode;
    float v;
    if (mode == 1)      v = (((const int*)p)[m] != 0) ? 1.f : 0.f;
    else if (mode == 2) v = (((const float*)p)[m] != 0.f) ? 1.f : 0.f;
    else                v = (((const unsigned char*)p)[m] != 0) ? 1.f : 0.f;
    g_msk[m] = v;
}

__global__ void init_kernel() {
    int i = blockIdx.x * blockDim.x + threadIdx.x;
    if (i < KPROT) { g_S[i] = 0.f; g_r[i] = 1.f; g_maxd[i] = 0; }
    if (i < MROWS) { g_c[i] = 1.f; }
    if (i < 4)     { g_acc[i] = 0.f; }
}

// ---------------- normalize / convert to fp16 -----------------------------------
// which: 0 -> g_th, 1 -> g_sh, 2 -> g_whn (normalized); 3 -> g_whr (raw convert)
__global__ void normalize_rows_kernel(const float* __restrict__ in, int which) {
    __half* out = (which == 0) ? g_th : (which == 1) ? g_sh : (which == 2) ? g_whn : g_whr;
    int row = blockIdx.x;
    const float* x = in + (size_t)row * DDIM;
    float inv = 1.f;
    if (which != 3) {
        float ss = 0.f;
        for (int d = threadIdx.x; d < DDIM; d += blockDim.x) { float v = x[d]; ss += v * v; }
        ss = blockSum(ss);
        __shared__ float sinv;
        if (threadIdx.x == 0) sinv = 1.f / fmaxf(sqrtf(ss), 1e-12f);
        __syncthreads();
        inv = sinv;
    }
    __half* o = out + (size_t)row * DDIM;
    for (int d = threadIdx.x; d < DDIM; d += blockDim.x) o[d] = __float2half(x[d] * inv);
}

// ---------------- warp-MMA fp16 GEMM (HMMA path; no tcgen05 on this target) -----
// C[M,N] = A[M,D] * B[N,D]^T. CTA tile 128x128, BK=32, 8 warps (64x32 warp tile).
// MODE 0: A=g_th, B=g_whr -> g_Lt + fused colsum S1
// MODE 1: A=g_sh, B=g_whr -> g_Ls
// MODE 2: A=B=g_whn -> no store, per-row off-diag max -> g_maxd

#define ROWB 80                 // smem bytes per 32-half row (+8 halves pad)
#define TILEB (128 * ROWB)      // 10240 bytes per tile buffer

__device__ __forceinline__ uint32_t smem_u32(const void* p) {
    uint32_t a;
    asm("{ .reg .u64 t; cvta.to.shared.u64 t, %1; cvt.u32.u64 %0, t; }" : "=r"(a) : "l"(p));
    return a;
}
__device__ __forceinline__ void ldsm_x4(uint32_t& r0, uint32_t& r1, uint32_t& r2, uint32_t& r3,
                                        uint32_t addr) {
    asm volatile("ldmatrix.sync.aligned.m8n8.x4.shared.b16 {%0,%1,%2,%3}, [%4];"
                 : "=r"(r0), "=r"(r1), "=r"(r2), "=r"(r3) : "r"(addr));
}
__device__ __forceinline__ void mma16816(float* c, uint32_t a0, uint32_t a1, uint32_t a2,
                                         uint32_t a3, uint32_t b0, uint32_t b1) {
    asm volatile("mma.sync.aligned.m16n8k16.row.col.f32.f16.f16.f32 "
                 "{%0,%1,%2,%3}, {%4,%5,%6,%7}, {%8,%9}, {%0,%1,%2,%3};"
                 : "+f"(c[0]), "+f"(c[1]), "+f"(c[2]), "+f"(c[3])
                 : "r"(a0), "r"(a1), "r"(a2), "r"(a3), "r"(b0), "r"(b1));
}
__device__ __forceinline__ void cpasync16(uint32_t dst, const void* src) {
    asm volatile("cp.async.cg.shared.global [%0], [%1], 16;" :: "r"(dst), "l"(src) : "memory");
}

template <int MODE>
__global__ void __launch_bounds__(256, 2)
gemm16_kernel() {
    __shared__ __align__(16) uint8_t smem[4 * TILEB];
    const __half* A = (MODE == 0) ? g_th : (MODE == 1) ? g_sh : g_whn;
    const __half* B = (MODE == 2) ? g_whn : g_whr;
    __half* C = (MODE == 0) ? g_Lt : g_Ls;

    int tid = threadIdx.x, wid = tid >> 5, lane = tid & 31;
    int m0 = blockIdx.y * 128, n0 = blockIdx.x * 128;
    int wm = (wid >> 2) * 64, wn = (wid & 3) * 32;

    uint32_t sb = smem_u32(smem);
    uint32_t sA[2] = {sb, sb + TILEB};
    uint32_t sB[2] = {sb + 2 * TILEB, sb + 3 * TILEB};

    float acc[4][4][4];
#pragma unroll
    for (int i = 0; i < 4; i++)
#pragma unroll
        for (int j = 0; j < 4; j++)
#pragma unroll
            for (int q = 0; q < 4; q++) acc[i][j][q] = 0.f;

    const __half* gA = A + (size_t)m0 * DDIM;
    const __half* gB = B + (size_t)n0 * DDIM;
    // load indices: 512 16B chunks per tile; this thread handles tid and tid+256
    int r0c = tid >> 2, q0c = tid & 3;          // chunk tid
    int r1c = (tid + 256) >> 2, q1c = tid & 3;  // chunk tid+256

    // ldmatrix lane addressing (within warp tile)
    int aRow = wm + (lane & 15);
    int aColB = (lane >> 4) * 16;
    int bRow = wn + (lane & 7) + ((lane >> 4) << 3);
    int bColB = ((lane >> 3) & 1) * 16;

#define LOAD_TILE(buf, kt) do {                                               \
    int koff = (kt) * 32;                                                     \
    cpasync16(sA[buf] + r0c * ROWB + q0c * 16, gA + (size_t)r0c * DDIM + koff + q0c * 8); \
    cpasync16(sB[buf] + r0c * ROWB + q0c * 16, gB + (size_t)r0c * DDIM + koff + q0c * 8); \
    cpasync16(sA[buf] + r1c * ROWB + q1c * 16, gA + (size_t)r1c * DDIM + koff + q1c * 8); \
    cpasync16(sB[buf] + r1c * ROWB + q1c * 16, gB + (size_t)r1c * DDIM + koff + q1c * 8); \
    asm volatile("cp.async.commit_group;" ::: "memory");                      \
} while (0)

    LOAD_TILE(0, 0);

    const int NKT = DDIM / 32;  // 24
#pragma unroll 1
    for (int kt = 0; kt < NKT; kt++) {
        int buf = kt & 1;
        if (kt + 1 < NKT) {
            LOAD_TILE(buf ^ 1, kt + 1);
            asm volatile("cp.async.wait_group 1;" ::: "memory");
        } else {
            asm volatile("cp.async.wait_group 0;" ::: "memory");
        }
        __syncthreads();
#pragma unroll
        for (int ks = 0; ks < 2; ks++) {
            uint32_t a[4][4], b[2][4];
#pragma unroll
            for (int mi = 0; mi < 4; mi++)
                ldsm_x4(a[mi][0], a[mi][1], a[mi][2], a[mi][3],
                        sA[buf] + (uint32_t)((aRow + mi * 16) * ROWB + ks * 32 + aColB));
#pragma unroll
            for (int np = 0; np < 2; np++)
                ldsm_x4(b[np][0], b[np][1], b[np][2], b[np][3],
                        sB[buf] + (uint32_t)((bRow + np * 16) * ROWB + ks * 32 + bColB));
#pragma unroll
            for (int mi = 0; mi < 4; mi++)
#pragma unroll
                for (int ni = 0; ni < 4; ni++) {
                    int np = ni >> 1, sel = (ni & 1) * 2;
                    mma16816(acc[mi][ni], a[mi][0], a[mi][1], a[mi][2], a[mi][3],
                             b[np][sel], b[np][sel + 1]);
                }
        }
        __syncthreads();
    }
#undef LOAD_TILE

    int tr = lane >> 2, tc = (lane & 3) * 2;

    if (MODE == 0 || MODE == 1) {
#pragma unroll
        for (int mi = 0; mi < 4; mi++) {
            int gr0 = m0 + wm + mi * 16 + tr;
#pragma unroll
            for (int ni = 0; ni < 4; ni++) {
                int gc = n0 + wn + ni * 8 + tc;
                __half2 h01 = __floats2half2_rn(acc[mi][ni][0], acc[mi][ni][1]);
                __half2 h23 = __floats2half2_rn(acc[mi][ni][2], acc[mi][ni][3]);
                *(__half2*)&C[(size_t)gr0 * KPROT + gc] = h01;
                *(__half2*)&C[(size_t)(gr0 + 8) * KPROT + gc] = h23;
            }
        }
    }
    if (MODE == 0) {
        // fused S1 column sums: sum_m exp(L/tt - shift) over this CTA's 128 rows
#pragma unroll
        for (int ni = 0; ni < 4; ni++) {
            float s0 = 0.f, s1 = 0.f;
#pragma unroll
            for (int mi = 0; mi < 4; mi++) {
                s0 += __expf(acc[mi][ni][0] * INV_TT - SHIFT)
                    + __expf(acc[mi][ni][2] * INV_TT - SHIFT);
                s1 += __expf(acc[mi][ni][1] * INV_TT - SHIFT)
                    + __expf(acc[mi][ni][3] * INV_TT - SHIFT);
            }
#pragma unroll
            for (int o = 4; o < 32; o <<= 1) {
                s0 += __shfl_down_sync(0xffffffffu, s0, o);
                s1 += __shfl_down_sync(0xffffffffu, s1, o);
            }
            if (lane < 4) {
                int gc = n0 + wn + ni * 8 + lane * 2;
                atomicAdd(&g_S[gc], s0);
                atomicAdd(&g_S[gc + 1], s1);
            }
        }
    }
    if (MODE == 2) {
#pragma unroll
        for (int mi = 0; mi < 4; mi++) {
            int gr0 = m0 + wm + mi * 16 + tr;
            int gr1 = gr0 + 8;
            float mx0 = -2.f, mx1 = -2.f;
#pragma unroll
            for (int ni = 0; ni < 4; ni++) {
                int gc = n0 + wn + ni * 8 + tc;
                mx0 = fmaxf(mx0, (gc == gr0) ? -2.f : acc[mi][ni][0]);
                mx0 = fmaxf(mx0, (gc + 1 == gr0) ? -2.f : acc[mi][ni][1]);
                mx1 = fmaxf(mx1, (gc == gr1) ? -2.f : acc[mi][ni][2]);
                mx1 = fmaxf(mx1, (gc + 1 == gr1) ? -2.f : acc[mi][ni][3]);
            }
#pragma unroll
            for (int o = 1; o < 4; o <<= 1) {
                mx0 = fmaxf(mx0, __shfl_xor_sync(0xffffffffu, mx0, o));
                mx1 = fmaxf(mx1, __shfl_xor_sync(0xffffffffu, mx1, o));
            }
            if ((lane & 3) == 0) {
                atomicMax(&g_maxd[gr0], __float_as_int(mx0 + 2.0f));
                atomicMax(&g_maxd[gr1], __float_as_int(mx1 + 2.0f));
            }
        }
    }
}

// ---------------- helpers --------------------------------------------------------
__device__ __forceinline__ void h8_to_f(const uint4& u, float f[8]) {
    __half2 a = *(const __half2*)&u.x, b = *(const __half2*)&u.y;
    __half2 c = *(const __half2*)&u.z, d = *(const __half2*)&u.w;
    float2 fa = __half22float2(a), fb = __half22float2(b);
    float2 fc = __half22float2(c), fd = __half22float2(d);
    f[0] = fa.x; f[1] = fa.y; f[2] = fb.x; f[3] = fb.y;
    f[4] = fc.x; f[5] = fc.y; f[6] = fd.x; f[7] = fd.y;
}

// ---------------- Sinkhorn passes --------------------------------------------------
__global__ void r_update_kernel() {
    int k = blockIdx.x * blockDim.x + threadIdx.x;
    if (k < KPROT) {
        float r = g_r[k], s = g_S[k];
        g_r[k] = r / (r * s + SK_EPS);
        g_S[k] = 0.f;
    }
}

__global__ void pass_T_kernel() {
    int m = blockIdx.x;
    const uint4* row = (const uint4*)(g_Lt + (size_t)m * KPROT);
    float t = 0.f;
    for (int i = threadIdx.x; i < KPROT / 8; i += blockDim.x) {
        uint4 u = row[i];
        float lt[8];
        h8_to_f(u, lt);
        float4 r0 = *(const float4*)(g_r + i * 8);
        float4 r1 = *(const float4*)(g_r + i * 8 + 4);
        float rr[8] = {r0.x, r0.y, r0.z, r0.w, r1.x, r1.y, r1.z, r1.w};
#pragma unroll
        for (int j = 0; j < 8; j++) t += __expf(lt[j] * INV_TT - SHIFT) * rr[j];
    }
    t = blockSum(t);
    if (threadIdx.x == 0) {
        float co = g_c[m];
        g_c[m] = co / (co * t + SK_EPS);
    }
}

__global__ void pass_S_kernel() {
    int k = blockIdx.x * blockDim.x + threadIdx.x;
    int m0 = blockIdx.y * 64;
    __shared__ float cs[64];
    if (threadIdx.x < 64) cs[threadIdx.x] = g_c[m0 + threadIdx.x];
    __syncthreads();
    float s = 0.f;
#pragma unroll 4
    for (int r = 0; r < 64; r++) {
        float lt = __half2float(g_Lt[(size_t)(m0 + r) * KPROT + k]);
        s += __expf(lt * INV_TT - SHIFT) * cs[r];
    }
    atomicAdd(&g_S[k], s);
}

// ---------------- fused loss pass ----------------------------------------------
__global__ void loss_kernel() {
    int m = blockIdx.x;
    const uint4* ltr = (const uint4*)(g_Lt + (size_t)m * KPROT);
    const uint4* lsr = (const uint4*)(g_Ls + (size_t)m * KPROT);
    float A = 0.f, Bv = 0.f, Dv = 0.f, Cv = 0.f, F = 0.f;
    for (int i = threadIdx.x; i < KPROT / 8; i += blockDim.x) {
        uint4 ut = ltr[i], us = lsr[i];
        float lt[8], ls[8];
        h8_to_f(ut, lt);
        h8_to_f(us, ls);
        float4 r0 = *(const float4*)(g_r + i * 8);
        float4 r1 = *(const float4*)(g_r + i * 8 + 4);
        float rr[8] = {r0.x, r0.y, r0.z, r0.w, r1.x, r1.y, r1.z, r1.w};
#pragma unroll
        for (int j = 0; j < 8; j++) {
            float e  = __expf(lt[j] * INV_TT - SHIFT);
            float er = e * rr[j];
            A  += er;
            Bv += er * lt[j];
            Dv += e;
            Cv += er * ls[j];
            F  += __expf(ls[j] * INV_ST);
        }
    }
    A  = blockSum(A);
    Bv = blockSum(Bv);
    Dv = blockSum(Dv);
    Cv = blockSum(Cv);
    F  = blockSum(F);
    if (threadIdx.x == 0) {
        float co = g_c[m];
        float c3 = co / (co * A + SK_EPS);
        float lse_t = logf(Dv) + SHIFT;
        float lse_s = logf(F);
        float tpt = c3 * (A * lse_t - Bv * INV_TT);
        float spt = c3 * (A * lse_s - Cv * INV_ST);
        atomicAdd(&g_acc[0], tpt);
        float mm = g_msk[m];
        atomicAdd(&g_acc[1], mm * spt);
        atomicAdd(&g_acc[2], mm);
    }
}

__global__ void koleo_kernel() {
    int k = blockIdx.x * blockDim.x + threadIdx.x;
    float term = 0.f;
    if (k < KPROT) {
        float g = __int_as_float(g_maxd[k]) - 2.0f;
        float d = sqrtf(fmaxf(2.f - 2.f * g, 0.f));
        term = logf(d + 1e-8f);
    }
    term = blockSum(term);
    if (threadIdx.x == 0) atomicAdd(&g_acc[3], term);
}

__global__ void finalize_kernel(float* __restrict__ out) {
    if (threadIdx.x == 0) {
        out[0] = g_acc[1] / fmaxf(g_acc[2], 1.f);
        out[1] = g_acc[0] * (1.f / (float)MROWS);
        out[2] = -g_acc[3] * (1.f / (float)KPROT);
    }
}

// ---------------- launch ------------------------------------------------------------
extern "C" void kernel_launch(void* const* d_in, const int* in_sizes, int n_in,
                              void* d_out, int out_size) {
    int midx = -1;
    for (int i = 0; i < n_in; i++)
        if (in_sizes[i] == MROWS) { midx = i; break; }
    if (midx < 0) midx = 2;
    int others[3], no = 0;
    for (int i = 0; i < n_in && no < 3; i++)
        if (i != midx) others[no++] = i;

    const float* teacher = (const float*)d_in[others[0]];
    const float* student = (const float*)d_in[others[1]];
    const float* W       = (const float*)d_in[others[2]];
    const void*  mask    = d_in[midx];

    detect_mask_kernel<<<1, 256>>>((const unsigned char*)mask);
    build_mask_kernel<<<32, 256>>>(mask);
    init_kernel<<<32, 256>>>();

    normalize_rows_kernel<<<MROWS, 256>>>(teacher, 0);
    normalize_rows_kernel<<<MROWS, 256>>>(student, 1);
    normalize_rows_kernel<<<KPROT, 256>>>(W, 2);   // normalized (koleo)
    normalize_rows_kernel<<<KPROT, 256>>>(W, 3);   // raw fp16 convert (logits)

    dim3 gg(KPROT / 128, MROWS / 128);
    gemm16_kernel<0><<<gg, 256>>>();   // teacher logits + fused S1
    gemm16_kernel<1><<<gg, 256>>>();   // student logits
    gemm16_kernel<2><<<gg, 256>>>();   // koleo nn-max

    // Sinkhorn: S1 fused -> r1 ; T -> c1 ; S2 -> r2 ; T -> c2 ; S3 -> r3 ; T3 fused in loss
    r_update_kernel<<<KPROT / 256, 256>>>();
    pass_T_kernel<<<MROWS, 256>>>();
    pass_S_kernel<<<dim3(KPROT / 256, MROWS / 64), 256>>>();
    r_update_kernel<<<KPROT / 256, 256>>>();
    pass_T_kernel<<<MROWS, 256>>>();
    pass_S_kernel<<<dim3(KPROT / 256, MROWS / 64), 256>>>();
    r_update_kernel<<<KPROT / 256, 256>>>();

    loss_kernel<<<MROWS, 256>>>();
    koleo_kernel<<<KPROT / 256, 256>>>();
    finalize_kernel<<<1, 32>>>((float*)d_out);
    (void)out_size;
}

// round 5
// speedup vs baseline: 5.7059x; 1.1749x over previous
#include <cuda_runtime.h>
#include <cuda_fp16.h>
#include <cstdint>

#define MROWS 8192   // B*N tokens
#define KPROT 8192   // prototypes
#define DDIM  768
#define INV_TT (1.0f/0.07f)
#define INV_ST 10.0f
#define SK_EPS 1e-8f
#define SHIFT  9.0f

// ---------------- scratch (static device globals; no allocation) -------------
static __device__ __align__(16) __half g_Lt[(size_t)MROWS * KPROT];
static __device__ __align__(16) __half g_Ls[(size_t)MROWS * KPROT];
static __device__ __align__(16) __half g_Et[(size_t)MROWS * KPROT];  // exp(Lt/tt - shift)
static __device__ __align__(16) __half g_th[MROWS * DDIM];
static __device__ __align__(16) __half g_sh[MROWS * DDIM];
static __device__ __align__(16) __half g_whr[KPROT * DDIM];
static __device__ __align__(16) __half g_whn[KPROT * DDIM];
static __device__ float  g_S[KPROT];
static __device__ float  g_r[KPROT];
static __device__ float  g_c[MROWS];
static __device__ float  g_msk[MROWS];
static __device__ int    g_maxd[KPROT];
static __device__ float  g_acc[4];
static __device__ int    g_maskmode;

// ---------------- reductions ---------------------------------------------------
__device__ __forceinline__ float warpSum(float v) {
#pragma unroll
    for (int o = 16; o > 0; o >>= 1) v += __shfl_down_sync(0xffffffffu, v, o);
    return v;
}
__device__ float blockSum(float v) {
    __shared__ float sb[32];
    int lane = threadIdx.x & 31, w = threadIdx.x >> 5;
    v = warpSum(v);
    __syncthreads();
    if (lane == 0) sb[w] = v;
    __syncthreads();
    int nw = (blockDim.x + 31) >> 5;
    v = (threadIdx.x < nw) ? sb[threadIdx.x] : 0.f;
    if (w == 0) v = warpSum(v);
    return v;
}

// ---------------- mask handling -------------------------------------------------
__global__ void detect_mask_kernel(const unsigned char* __restrict__ p) {
    __shared__ int c0, c1, c23;
    if (threadIdx.x == 0) { c0 = 0; c1 = 0; c23 = 0; }
    __syncthreads();
    int l0 = 0, l1 = 0, l23 = 0;
    for (int i = threadIdx.x; i < MROWS; i += blockDim.x) {
        unsigned char b = p[i];
        if (b) { int r = i & 3; if (r == 0) l0++; else if (r == 1) l1++; else l23++; }
    }
    atomicAdd(&c0, l0); atomicAdd(&c1, l1); atomicAdd(&c23, l23);
    __syncthreads();
    if (threadIdx.x == 0) {
        int mode;
        if (c1 == 0 && c23 == 0) mode = (c0 > 0) ? 1 : 0;
        else if (c1 == 0)        mode = 2;
        else                     mode = 0;
        g_maskmode = mode;
    }
}
__global__ void build_mask_kernel(const void* __restrict__ p) {
    int m = blockIdx.x * blockDim.x + threadIdx.x;
    if (m >= MROWS) return;
    int mode = g_maskmode;
    float v;
    if (mode == 1)      v = (((const int*)p)[m] != 0) ? 1.f : 0.f;
    else if (mode == 2) v = (((const float*)p)[m] != 0.f) ? 1.f : 0.f;
    else                v = (((const unsigned char*)p)[m] != 0) ? 1.f : 0.f;
    g_msk[m] = v;
}

__global__ void init_kernel() {
    int i = blockIdx.x * blockDim.x + threadIdx.x;
    if (i < KPROT) { g_S[i] = 0.f; g_r[i] = 1.f; g_maxd[i] = 0; }
    if (i < MROWS) { g_c[i] = 1.f; }
    if (i < 4)     { g_acc[i] = 0.f; }
}

// ---------------- normalize: warp-per-row, 3 segments in one launch --------------
__global__ void __launch_bounds__(256)
norm_all_kernel(const float* __restrict__ t, const float* __restrict__ s,
                const float* __restrict__ w) {
    int wid = threadIdx.x >> 5, lane = threadIdx.x & 31;
    int row = blockIdx.x * 8 + wid;
    int seg = blockIdx.y;
    const float* in = (seg == 0) ? t : (seg == 1) ? s : w;
    __half* outN = (seg == 0) ? g_th : (seg == 1) ? g_sh : g_whn;
    const float4* x = (const float4*)(in + (size_t)row * DDIM);
    float4 v[6];
    float ss = 0.f;
#pragma unroll
    for (int i = 0; i < 6; i++) {
        v[i] = x[i * 32 + lane];
        ss += v[i].x * v[i].x + v[i].y * v[i].y + v[i].z * v[i].z + v[i].w * v[i].w;
    }
#pragma unroll
    for (int o = 16; o > 0; o >>= 1) ss += __shfl_xor_sync(0xffffffffu, ss, o);
    float inv = 1.f / fmaxf(sqrtf(ss), 1e-12f);
    uint2* oN = (uint2*)(outN + (size_t)row * DDIM);
#pragma unroll
    for (int i = 0; i < 6; i++) {
        __half2 h0 = __floats2half2_rn(v[i].x * inv, v[i].y * inv);
        __half2 h1 = __floats2half2_rn(v[i].z * inv, v[i].w * inv);
        uint2 u; u.x = *(uint32_t*)&h0; u.y = *(uint32_t*)&h1;
        oN[i * 32 + lane] = u;
    }
    if (seg == 2) {
        uint2* oR = (uint2*)(g_whr + (size_t)row * DDIM);
#pragma unroll
        for (int i = 0; i < 6; i++) {
            __half2 h0 = __floats2half2_rn(v[i].x, v[i].y);
            __half2 h1 = __floats2half2_rn(v[i].z, v[i].w);
            uint2 u; u.x = *(uint32_t*)&h0; u.y = *(uint32_t*)&h1;
            oR[i * 32 + lane] = u;
        }
    }
}

// ---------------- warp-MMA fp16 GEMM, all 3 products in ONE launch ----------------
// blockIdx.z: 0: g_th x g_whr^T -> g_Lt + g_Et + fused S1 colsum
//             1: g_sh x g_whr^T -> g_Ls
//             2: g_whn x g_whn^T (symmetric, lower triangle) -> row/col max g_maxd

#define ROWB 80
#define TILEB (128 * ROWB)

__device__ __forceinline__ uint32_t smem_u32(const void* p) {
    uint32_t a;
    asm("{ .reg .u64 t; cvta.to.shared.u64 t, %1; cvt.u32.u64 %0, t; }" : "=r"(a) : "l"(p));
    return a;
}
__device__ __forceinline__ void ldsm_x4(uint32_t& r0, uint32_t& r1, uint32_t& r2, uint32_t& r3,
                                        uint32_t addr) {
    asm volatile("ldmatrix.sync.aligned.m8n8.x4.shared.b16 {%0,%1,%2,%3}, [%4];"
                 : "=r"(r0), "=r"(r1), "=r"(r2), "=r"(r3) : "r"(addr));
}
__device__ __forceinline__ void mma16816(float* c, uint32_t a0, uint32_t a1, uint32_t a2,
                                         uint32_t a3, uint32_t b0, uint32_t b1) {
    asm volatile("mma.sync.aligned.m16n8k16.row.col.f32.f16.f16.f32 "
                 "{%0,%1,%2,%3}, {%4,%5,%6,%7}, {%8,%9}, {%0,%1,%2,%3};"
                 : "+f"(c[0]), "+f"(c[1]), "+f"(c[2]), "+f"(c[3])
                 : "r"(a0), "r"(a1), "r"(a2), "r"(a3), "r"(b0), "r"(b1));
}
__device__ __forceinline__ void cpasync16(uint32_t dst, const void* src) {
    asm volatile("cp.async.cg.shared.global [%0], [%1], 16;" :: "r"(dst), "l"(src) : "memory");
}

__global__ void __launch_bounds__(256, 2)
gemm_all_kernel() {
    const int mode = blockIdx.z;
    if (mode == 2 && blockIdx.x > blockIdx.y) return;  // symmetric: lower triangle only

    __shared__ __align__(16) uint8_t smem[4 * TILEB];
    const __half* A = (mode == 0) ? g_th : (mode == 1) ? g_sh : g_whn;
    const __half* B = (mode == 2) ? g_whn : g_whr;
    __half* C = (mode == 0) ? g_Lt : g_Ls;

    int tid = threadIdx.x, wid = tid >> 5, lane = tid & 31;
    int m0 = blockIdx.y * 128, n0 = blockIdx.x * 128;
    int wm = (wid >> 2) * 64, wn = (wid & 3) * 32;

    uint32_t sb = smem_u32(smem);
    uint32_t sA[2] = {sb, sb + TILEB};
    uint32_t sB[2] = {sb + 2 * TILEB, sb + 3 * TILEB};

    float acc[4][4][4];
#pragma unroll
    for (int i = 0; i < 4; i++)
#pragma unroll
        for (int j = 0; j < 4; j++)
#pragma unroll
            for (int q = 0; q < 4; q++) acc[i][j][q] = 0.f;

    const __half* gA = A + (size_t)m0 * DDIM;
    const __half* gB = B + (size_t)n0 * DDIM;
    int r0c = tid >> 2, q0c = tid & 3;
    int r1c = (tid + 256) >> 2, q1c = tid & 3;

    int aRow = wm + (lane & 15);
    int aColB = (lane >> 4) * 16;
    int bRow = wn + (lane & 7) + ((lane >> 4) << 3);
    int bColB = ((lane >> 3) & 1) * 16;

#define LOAD_TILE(buf, kt) do {                                               \
    int koff = (kt) * 32;                                                     \
    cpasync16(sA[buf] + r0c * ROWB + q0c * 16, gA + (size_t)r0c * DDIM + koff + q0c * 8); \
    cpasync16(sB[buf] + r0c * ROWB + q0c * 16, gB + (size_t)r0c * DDIM + koff + q0c * 8); \
    cpasync16(sA[buf] + r1c * ROWB + q1c * 16, gA + (size_t)r1c * DDIM + koff + q1c * 8); \
    cpasync16(sB[buf] + r1c * ROWB + q1c * 16, gB + (size_t)r1c * DDIM + koff + q1c * 8); \
    asm volatile("cp.async.commit_group;" ::: "memory");                      \
} while (0)

    LOAD_TILE(0, 0);

    const int NKT = DDIM / 32;
#pragma unroll 1
    for (int kt = 0; kt < NKT; kt++) {
        int buf = kt & 1;
        if (kt + 1 < NKT) {
            LOAD_TILE(buf ^ 1, kt + 1);
            asm volatile("cp.async.wait_group 1;" ::: "memory");
        } else {
            asm volatile("cp.async.wait_group 0;" ::: "memory");
        }
        __syncthreads();
#pragma unroll
        for (int ks = 0; ks < 2; ks++) {
            uint32_t a[4][4], b[2][4];
#pragma unroll
            for (int mi = 0; mi < 4; mi++)
                ldsm_x4(a[mi][0], a[mi][1], a[mi][2], a[mi][3],
                        sA[buf] + (uint32_t)((aRow + mi * 16) * ROWB + ks * 32 + aColB));
#pragma unroll
            for (int np = 0; np < 2; np++)
                ldsm_x4(b[np][0], b[np][1], b[np][2], b[np][3],
                        sB[buf] + (uint32_t)((bRow + np * 16) * ROWB + ks * 32 + bColB));
#pragma unroll
            for (int mi = 0; mi < 4; mi++)
#pragma unroll
                for (int ni = 0; ni < 4; ni++) {
                    int np = ni >> 1, sel = (ni & 1) * 2;
                    mma16816(acc[mi][ni], a[mi][0], a[mi][1], a[mi][2], a[mi][3],
                             b[np][sel], b[np][sel + 1]);
                }
        }
        __syncthreads();
    }
#undef LOAD_TILE

    int tr = lane >> 2, tc = (lane & 3) * 2;

    if (mode == 0) {
        // store logits + E = exp(L/tt - shift) + fused colsum S1
#pragma unroll
        for (int mi = 0; mi < 4; mi++) {
            int gr0 = m0 + wm + mi * 16 + tr;
#pragma unroll
            for (int ni = 0; ni < 4; ni++) {
                int gc = n0 + wn + ni * 8 + tc;
                float e0 = __expf(acc[mi][ni][0] * INV_TT - SHIFT);
                float e1 = __expf(acc[mi][ni][1] * INV_TT - SHIFT);
                float e2 = __expf(acc[mi][ni][2] * INV_TT - SHIFT);
                float e3 = __expf(acc[mi][ni][3] * INV_TT - SHIFT);
                *(__half2*)&C[(size_t)gr0 * KPROT + gc] =
                    __floats2half2_rn(acc[mi][ni][0], acc[mi][ni][1]);
                *(__half2*)&C[(size_t)(gr0 + 8) * KPROT + gc] =
                    __floats2half2_rn(acc[mi][ni][2], acc[mi][ni][3]);
                *(__half2*)&g_Et[(size_t)gr0 * KPROT + gc] = __floats2half2_rn(e0, e1);
                *(__half2*)&g_Et[(size_t)(gr0 + 8) * KPROT + gc] = __floats2half2_rn(e2, e3);
                // stash exps back into acc for the colsum below
                acc[mi][ni][0] = e0; acc[mi][ni][1] = e1;
                acc[mi][ni][2] = e2; acc[mi][ni][3] = e3;
            }
        }
#pragma unroll
        for (int ni = 0; ni < 4; ni++) {
            float s0 = 0.f, s1 = 0.f;
#pragma unroll
            for (int mi = 0; mi < 4; mi++) {
                s0 += acc[mi][ni][0] + acc[mi][ni][2];
                s1 += acc[mi][ni][1] + acc[mi][ni][3];
            }
#pragma unroll
            for (int o = 4; o < 32; o <<= 1) {
                s0 += __shfl_down_sync(0xffffffffu, s0, o);
                s1 += __shfl_down_sync(0xffffffffu, s1, o);
            }
            if (lane < 4) {
                int gc = n0 + wn + ni * 8 + lane * 2;
                atomicAdd(&g_S[gc], s0);
                atomicAdd(&g_S[gc + 1], s1);
            }
        }
    } else if (mode == 1) {
#pragma unroll
        for (int mi = 0; mi < 4; mi++) {
            int gr0 = m0 + wm + mi * 16 + tr;
#pragma unroll
            for (int ni = 0; ni < 4; ni++) {
                int gc = n0 + wn + ni * 8 + tc;
                *(__half2*)&C[(size_t)gr0 * KPROT + gc] =
                    __floats2half2_rn(acc[mi][ni][0], acc[mi][ni][1]);
                *(__half2*)&C[(size_t)(gr0 + 8) * KPROT + gc] =
                    __floats2half2_rn(acc[mi][ni][2], acc[mi][ni][3]);
            }
        }
    } else {
        float cm[4][2];
#pragma unroll
        for (int ni = 0; ni < 4; ni++) { cm[ni][0] = -2.f; cm[ni][1] = -2.f; }
#pragma unroll
        for (int mi = 0; mi < 4; mi++) {
            int gr0 = m0 + wm + mi * 16 + tr;
            int gr1 = gr0 + 8;
            float mx0 = -2.f, mx1 = -2.f;
#pragma unroll
            for (int ni = 0; ni < 4; ni++) {
                int gc = n0 + wn + ni * 8 + tc;
                float v0 = (gc == gr0) ? -2.f : acc[mi][ni][0];
                float v1 = (gc + 1 == gr0) ? -2.f : acc[mi][ni][1];
                float v2 = (gc == gr1) ? -2.f : acc[mi][ni][2];
                float v3 = (gc + 1 == gr1) ? -2.f : acc[mi][ni][3];
                mx0 = fmaxf(mx0, fmaxf(v0, v1));
                mx1 = fmaxf(mx1, fmaxf(v2, v3));
                cm[ni][0] = fmaxf(cm[ni][0], fmaxf(v0, v2));
                cm[ni][1] = fmaxf(cm[ni][1], fmaxf(v1, v3));
            }
#pragma unroll
            for (int o = 1; o < 4; o <<= 1) {
                mx0 = fmaxf(mx0, __shfl_xor_sync(0xffffffffu, mx0, o));
                mx1 = fmaxf(mx1, __shfl_xor_sync(0xffffffffu, mx1, o));
            }
            if ((lane & 3) == 0) {
                atomicMax(&g_maxd[gr0], __float_as_int(mx0 + 2.0f));
                atomicMax(&g_maxd[gr1], __float_as_int(mx1 + 2.0f));
            }
        }
        // mirrored (upper-triangle) coverage via column maxes
#pragma unroll
        for (int ni = 0; ni < 4; ni++) {
            float c0 = cm[ni][0], c1 = cm[ni][1];
#pragma unroll
            for (int o = 4; o < 32; o <<= 1) {
                c0 = fmaxf(c0, __shfl_xor_sync(0xffffffffu, c0, o));
                c1 = fmaxf(c1, __shfl_xor_sync(0xffffffffu, c1, o));
            }
            if (lane < 4) {
                int gc = n0 + wn + ni * 8 + lane * 2;
                atomicMax(&g_maxd[gc], __float_as_int(c0 + 2.0f));
                atomicMax(&g_maxd[gc + 1], __float_as_int(c1 + 2.0f));
            }
        }
    }
}

// ---------------- helpers --------------------------------------------------------
__device__ __forceinline__ void h8_to_f(const uint4& u, float f[8]) {
    __half2 a = *(const __half2*)&u.x, b = *(const __half2*)&u.y;
    __half2 c = *(const __half2*)&u.z, d = *(const __half2*)&u.w;
    float2 fa = __half22float2(a), fb = __half22float2(b);
    float2 fc = __half22float2(c), fd = __half22float2(d);
    f[0] = fa.x; f[1] = fa.y; f[2] = fb.x; f[3] = fb.y;
    f[4] = fc.x; f[5] = fc.y; f[6] = fd.x; f[7] = fd.y;
}

// ---------------- Sinkhorn passes (exp-free: use stored E) -------------------------
__global__ void r_update_kernel() {
    int k = blockIdx.x * blockDim.x + threadIdx.x;
    if (k < KPROT) {
        float r = g_r[k], s = g_S[k];
        g_r[k] = r / (r * s + SK_EPS);
        g_S[k] = 0.f;
    }
}

__global__ void pass_T_kernel() {
    int m = blockIdx.x;
    const uint4* row = (const uint4*)(g_Et + (size_t)m * KPROT);
    float t = 0.f;
    for (int i = threadIdx.x; i < KPROT / 8; i += blockDim.x) {
        uint4 u = row[i];
        float ev[8];
        h8_to_f(u, ev);
        float4 r0 = *(const float4*)(g_r + i * 8);
        float4 r1 = *(const float4*)(g_r + i * 8 + 4);
        t += ev[0] * r0.x + ev[1] * r0.y + ev[2] * r0.z + ev[3] * r0.w
           + ev[4] * r1.x + ev[5] * r1.y + ev[6] * r1.z + ev[7] * r1.w;
    }
    t = blockSum(t);
    if (threadIdx.x == 0) {
        float co = g_c[m];
        g_c[m] = co / (co * t + SK_EPS);
    }
}

__global__ void pass_S_kernel() {
    int k = blockIdx.x * blockDim.x + threadIdx.x;
    int m0 = blockIdx.y * 64;
    __shared__ float cs[64];
    if (threadIdx.x < 64) cs[threadIdx.x] = g_c[m0 + threadIdx.x];
    __syncthreads();
    float s = 0.f;
#pragma unroll 8
    for (int r = 0; r < 64; r++) {
        float ev = __half2float(g_Et[(size_t)(m0 + r) * KPROT + k]);
        s = fmaf(ev, cs[r], s);
    }
    atomicAdd(&g_S[k], s);
}

// ---------------- fused loss pass ----------------------------------------------
__global__ void loss_kernel() {
    int m = blockIdx.x;
    const uint4* etr = (const uint4*)(g_Et + (size_t)m * KPROT);
    const uint4* ltr = (const uint4*)(g_Lt + (size_t)m * KPROT);
    const uint4* lsr = (const uint4*)(g_Ls + (size_t)m * KPROT);
    float A = 0.f, Bv = 0.f, Dv = 0.f, Cv = 0.f, F = 0.f;
    for (int i = threadIdx.x; i < KPROT / 8; i += blockDim.x) {
        uint4 ue = etr[i], ut = ltr[i], us = lsr[i];
        float ev[8], lt[8], ls[8];
        h8_to_f(ue, ev);
        h8_to_f(ut, lt);
        h8_to_f(us, ls);
        float4 r0 = *(const float4*)(g_r + i * 8);
        float4 r1 = *(const float4*)(g_r + i * 8 + 4);
        float rr[8] = {r0.x, r0.y, r0.z, r0.w, r1.x, r1.y, r1.z, r1.w};
#pragma unroll
        for (int j = 0; j < 8; j++) {
            float e  = ev[j];
            float er = e * rr[j];
            A  += er;
            Bv = fmaf(er, lt[j], Bv);
            Dv += e;
            Cv = fmaf(er, ls[j], Cv);
            F  += __expf(ls[j] * INV_ST);
        }
    }
    A  = blockSum(A);
    Bv = blockSum(Bv);
    Dv = blockSum(Dv);
    Cv = blockSum(Cv);
    F  = blockSum(F);
    if (threadIdx.x == 0) {
        float co = g_c[m];
        float c3 = co / (co * A + SK_EPS);
        float lse_t = logf(Dv) + SHIFT;
        float lse_s = logf(F);
        float tpt = c3 * (A * lse_t - Bv * INV_TT);
        float spt = c3 * (A * lse_s - Cv * INV_ST);
        atomicAdd(&g_acc[0], tpt);
        float mm = g_msk[m];
        atomicAdd(&g_acc[1], mm * spt);
        atomicAdd(&g_acc[2], mm);
    }
}

__global__ void koleo_kernel() {
    int k = blockIdx.x * blockDim.x + threadIdx.x;
    float term = 0.f;
    if (k < KPROT) {
        float g = __int_as_float(g_maxd[k]) - 2.0f;
        float d = sqrtf(fmaxf(2.f - 2.f * g, 0.f));
        term = logf(d + 1e-8f);
    }
    term = blockSum(term);
    if (threadIdx.x == 0) atomicAdd(&g_acc[3], term);
}

__global__ void finalize_kernel(float* __restrict__ out) {
    if (threadIdx.x == 0) {
        out[0] = g_acc[1] / fmaxf(g_acc[2], 1.f);
        out[1] = g_acc[0] * (1.f / (float)MROWS);
        out[2] = -g_acc[3] * (1.f / (float)KPROT);
    }
}

// ---------------- launch (single stream, fused GEMM launch) ------------------------
extern "C" void kernel_launch(void* const* d_in, const int* in_sizes, int n_in,
                              void* d_out, int out_size) {
    int midx = -1;
    for (int i = 0; i < n_in; i++)
        if (in_sizes[i] == MROWS) { midx = i; break; }
    if (midx < 0) midx = 2;
    int others[3], no = 0;
    for (int i = 0; i < n_in && no < 3; i++)
        if (i != midx) others[no++] = i;

    const float* teacher = (const float*)d_in[others[0]];
    const float* student = (const float*)d_in[others[1]];
    const float* W       = (const float*)d_in[others[2]];
    const void*  mask    = d_in[midx];

    detect_mask_kernel<<<1, 256>>>((const unsigned char*)mask);
    build_mask_kernel<<<32, 256>>>(mask);
    init_kernel<<<32, 256>>>();

    norm_all_kernel<<<dim3(MROWS / 8, 3), 256>>>(teacher, student, W);

    // all three GEMMs in one launch: z=0 teacher(+E+S1), z=1 student, z=2 koleo
    gemm_all_kernel<<<dim3(KPROT / 128, MROWS / 128, 3), 256>>>();

    // Sinkhorn: S1 fused -> r1 ; T -> c1 ; S2 -> r2 ; T -> c2 ; S3 -> r3 ; T3 fused in loss
    r_update_kernel<<<KPROT / 256, 256>>>();
    pass_T_kernel<<<MROWS, 256>>>();
    pass_S_kernel<<<dim3(KPROT / 256, MROWS / 64), 256>>>();
    r_update_kernel<<<KPROT / 256, 256>>>();
    pass_T_kernel<<<MROWS, 256>>>();
    pass_S_kernel<<<dim3(KPROT / 256, MROWS / 64), 256>>>();
    r_update_kernel<<<KPROT / 256, 256>>>();

    loss_kernel<<<MROWS, 256>>>();
    koleo_kernel<<<KPROT / 256, 256>>>();
    finalize_kernel<<<1, 32>>>((float*)d_out);
    (void)out_size;
}